// round 1
// baseline (speedup 1.0000x reference)
#include <cuda_runtime.h>
#include <cstddef>

#define F 128
#define MAXN 40000
#define MAXE 640000

// Scratch (no cudaMalloc allowed): ~67 MB of __device__ globals.
__device__ float g_pd[(size_t)MAXN * F];     // proj_dst + b1
__device__ float g_ps[(size_t)MAXN * F];     // proj_src
__device__ float g_sc[MAXE];                 // edge scores
__device__ float g_ex[MAXE];                 // exp(score - max) per edge
__device__ float g_neigh[(size_t)MAXN * F];  // attention-weighted neighborhood
__device__ int   g_rp[MAXN + 1];             // CSR row ptr over sorted dst

// ---------------------------------------------------------------------------
// GEMM: C[M x 128] = A[M x K] @ B[K x 128] (+ bias) (+= C if accum)
// Block tile 64x128, 256 threads, per-thread 4x8, BK=16. M must be mult of 64,
// K mult of 16 (holds: M=40000, K=128).
// ---------------------------------------------------------------------------
__global__ void __launch_bounds__(256) gemm_64x128(
    const float* __restrict__ A, const float* __restrict__ B,
    float* __restrict__ C, const float* __restrict__ bias,
    int K, int accum)
{
    __shared__ float As[16][68];   // [k][m], padded
    __shared__ float Bs[16][128];  // [k][n]

    const int tid = threadIdx.x;
    const int m0  = blockIdx.x * 64;
    const int tx  = tid & 15;   // output cols: tx*8 .. tx*8+7
    const int ty  = tid >> 4;   // output rows: ty*4 .. ty*4+3
    const int bc  = tx * 8;

    float acc[4][8];
#pragma unroll
    for (int i = 0; i < 4; i++)
#pragma unroll
        for (int j = 0; j < 8; j++) acc[i][j] = 0.f;

    const int ar = tid >> 2;        // A tile row 0..63
    const int ak = (tid & 3) * 4;   // A tile k offset (float4)
    const int bk = tid >> 4;        // B tile row 0..15

    for (int k0 = 0; k0 < K; k0 += 16) {
        float4 av  = *(const float4*)(A + (size_t)(m0 + ar) * K + k0 + ak);
        float4 bv0 = *(const float4*)(B + (size_t)(k0 + bk) * 128 + bc);
        float4 bv1 = *(const float4*)(B + (size_t)(k0 + bk) * 128 + bc + 4);
        __syncthreads();
        As[ak + 0][ar] = av.x;
        As[ak + 1][ar] = av.y;
        As[ak + 2][ar] = av.z;
        As[ak + 3][ar] = av.w;
        *(float4*)&Bs[bk][bc]     = bv0;
        *(float4*)&Bs[bk][bc + 4] = bv1;
        __syncthreads();
#pragma unroll
        for (int kk = 0; kk < 16; kk++) {
            float4 a  = *(const float4*)&As[kk][ty * 4];
            float4 b0 = *(const float4*)&Bs[kk][bc];
            float4 b1 = *(const float4*)&Bs[kk][bc + 4];
            float ra[4] = {a.x, a.y, a.z, a.w};
            float rb[8] = {b0.x, b0.y, b0.z, b0.w, b1.x, b1.y, b1.z, b1.w};
#pragma unroll
            for (int i = 0; i < 4; i++)
#pragma unroll
                for (int j = 0; j < 8; j++) acc[i][j] = fmaf(ra[i], rb[j], acc[i][j]);
        }
    }

    float bv[8];
#pragma unroll
    for (int j = 0; j < 8; j++) bv[j] = bias ? bias[bc + j] : 0.f;

#pragma unroll
    for (int i = 0; i < 4; i++) {
        float* crow = C + (size_t)(m0 + ty * 4 + i) * 128 + bc;
        float4 v0, v1;
        v0.x = acc[i][0] + bv[0]; v0.y = acc[i][1] + bv[1];
        v0.z = acc[i][2] + bv[2]; v0.w = acc[i][3] + bv[3];
        v1.x = acc[i][4] + bv[4]; v1.y = acc[i][5] + bv[5];
        v1.z = acc[i][6] + bv[6]; v1.w = acc[i][7] + bv[7];
        if (accum) {
            float4 c0 = *(const float4*)(crow);
            float4 c1 = *(const float4*)(crow + 4);
            v0.x += c0.x; v0.y += c0.y; v0.z += c0.z; v0.w += c0.w;
            v1.x += c1.x; v1.y += c1.y; v1.z += c1.z; v1.w += c1.w;
        }
        *(float4*)(crow)     = v0;
        *(float4*)(crow + 4) = v1;
    }
}

// ---------------------------------------------------------------------------
// row_ptr[n] = lower_bound(dst, n); dst is sorted. rp[N] = E.
// ---------------------------------------------------------------------------
__global__ void rowptr_kernel(const int* __restrict__ dst, int n, int E)
{
    int t = blockIdx.x * blockDim.x + threadIdx.x;
    if (t > n) return;
    int lo = 0, hi = E;
    while (lo < hi) {
        int mid = (lo + hi) >> 1;
        if (dst[mid] < t) lo = mid + 1; else hi = mid;
    }
    g_rp[t] = lo;
}

// ---------------------------------------------------------------------------
// Per-edge attention score: sc[e] = sum_k w2[k] * tanh(pd[dst,k] + ps[src,k])
// (b1 folded into pd; b2 cancels in softmax.) One warp per edge, float4/lane.
// ---------------------------------------------------------------------------
__global__ void __launch_bounds__(256) score_kernel(
    const int* __restrict__ src, const int* __restrict__ dst,
    const float* __restrict__ w2, int E)
{
    int e    = (blockIdx.x * blockDim.x + threadIdx.x) >> 5;
    int lane = threadIdx.x & 31;
    if (e >= E) return;
    int d = dst[e], s = src[e];
    float4 a = ((const float4*)(g_pd + (size_t)d * F))[lane];
    float4 b = ((const float4*)(g_ps + (size_t)s * F))[lane];
    float4 w = ((const float4*)w2)[lane];
    float acc = w.x * tanhf(a.x + b.x)
              + w.y * tanhf(a.y + b.y)
              + w.z * tanhf(a.z + b.z)
              + w.w * tanhf(a.w + b.w);
#pragma unroll
    for (int o = 16; o; o >>= 1) acc += __shfl_xor_sync(0xffffffffu, acc, o);
    if (lane == 0) g_sc[e] = acc;
}

// ---------------------------------------------------------------------------
// Segmented softmax + weighted neighbor aggregation. Block(128) per node.
// neigh[n,k] = sum_e exp(sc[e]-max)/den * feat[src[e],k]
// ---------------------------------------------------------------------------
__global__ void __launch_bounds__(128) softagg_kernel(
    const float* __restrict__ feat, const int* __restrict__ src)
{
    int node = blockIdx.x;
    int tid  = threadIdx.x;
    int r0 = g_rp[node], r1 = g_rp[node + 1];
    __shared__ float red[4];

    // segment max
    float m = -3.402823466e38f;
    for (int e = r0 + tid; e < r1; e += 128) m = fmaxf(m, g_sc[e]);
#pragma unroll
    for (int o = 16; o; o >>= 1) m = fmaxf(m, __shfl_xor_sync(0xffffffffu, m, o));
    if ((tid & 31) == 0) red[tid >> 5] = m;
    __syncthreads();
    m = fmaxf(fmaxf(red[0], red[1]), fmaxf(red[2], red[3]));
    __syncthreads();

    // exp and segment sum
    float sum = 0.f;
    for (int e = r0 + tid; e < r1; e += 128) {
        float v = __expf(g_sc[e] - m);
        g_ex[e] = v;
        sum += v;
    }
#pragma unroll
    for (int o = 16; o; o >>= 1) sum += __shfl_xor_sync(0xffffffffu, sum, o);
    if ((tid & 31) == 0) red[tid >> 5] = sum;
    __syncthreads();           // also orders g_ex writes before the agg reads
    sum = red[0] + red[1] + red[2] + red[3];
    float inv = (r1 > r0) ? (1.0f / sum) : 0.f;

    // weighted aggregation: thread tid owns feature tid
    float acc = 0.f;
    for (int e = r0; e < r1; e++) {
        float w = g_ex[e];
        acc = fmaf(w, feat[(size_t)src[e] * F + tid], acc);
    }
    g_neigh[(size_t)node * F + tid] = acc * inv;
}

// ---------------------------------------------------------------------------
extern "C" void kernel_launch(void* const* d_in, const int* in_sizes, int n_in,
                              void* d_out, int out_size)
{
    const float* feat = (const float*)d_in[0];
    const int*   src  = (const int*)d_in[1];
    const int*   dst  = (const int*)d_in[2];
    const float* w1   = (const float*)d_in[3];
    const float* b1   = (const float*)d_in[4];
    const float* w2   = (const float*)d_in[5];
    // d_in[6] = b2: cancels in softmax, unused
    const float* wf   = (const float*)d_in[7];
    const float* bf   = (const float*)d_in[8];
    float* out = (float*)d_out;

    const int N = in_sizes[0] / F;   // 40000
    const int E = in_sizes[1];       // 640000

    float *pd, *ps, *neigh;
    cudaGetSymbolAddress((void**)&pd,    g_pd);
    cudaGetSymbolAddress((void**)&ps,    g_ps);
    cudaGetSymbolAddress((void**)&neigh, g_neigh);

    const int gemm_blocks = N / 64;  // 625

    // 1) proj_dst = feat @ w1[:F] + b1 ; proj_src = feat @ w1[F:]
    gemm_64x128<<<gemm_blocks, 256>>>(feat, w1,              pd, b1,   F, 0);
    gemm_64x128<<<gemm_blocks, 256>>>(feat, w1 + F * F,      ps, NULL, F, 0);

    // 2) CSR row pointers over sorted dst
    rowptr_kernel<<<(N + 1 + 255) / 256, 256>>>(dst, N, E);

    // 3) per-edge attention scores (warp per edge)
    score_kernel<<<(E + 7) / 8, 256>>>(src, dst, w2, E);

    // 4) segmented softmax + weighted aggregation
    softagg_kernel<<<N, 128>>>(feat, src);

    // 5) rst = feat @ wf[:F] + bf ; rst += neigh @ wf[F:]
    gemm_64x128<<<gemm_blocks, 256>>>(feat,  wf,             out, bf,   F, 0);
    gemm_64x128<<<gemm_blocks, 256>>>(neigh, wf + F * F,     out, NULL, F, 1);
}

// round 2
// speedup vs baseline: 1.5641x; 1.5641x over previous
#include <cuda_runtime.h>
#include <cstddef>
#include <cstdint>

#define F 128
#define MAXN 40000
#define MAXE 640000

// Scratch (no cudaMalloc allowed): __device__ globals.
__device__ float g_pd[(size_t)MAXN * F];     // proj_dst + b1
__device__ float g_ps[(size_t)MAXN * F];     // proj_src
__device__ float g_sc[MAXE];                 // edge scores
__device__ float g_ex[MAXE];                 // exp(score - max) per edge
__device__ float g_neigh[(size_t)MAXN * F];  // attention-weighted neighborhood
__device__ int   g_rp[MAXN + 1];             // CSR row ptr over sorted dst

// ---------------------------------------------------------------------------
// tf32 helpers
// ---------------------------------------------------------------------------
__device__ __forceinline__ uint32_t f2tf(float x) {
    uint32_t r;
    asm("cvt.rna.tf32.f32 %0, %1;" : "=r"(r) : "f"(x));
    return r;
}

__device__ __forceinline__ void mma_tf32(float* c,
    uint32_t a0, uint32_t a1, uint32_t a2, uint32_t a3,
    uint32_t b0, uint32_t b1)
{
    asm("mma.sync.aligned.m16n8k8.row.col.f32.tf32.tf32.f32 "
        "{%0,%1,%2,%3}, {%4,%5,%6,%7}, {%8,%9}, {%0,%1,%2,%3};"
        : "+f"(c[0]), "+f"(c[1]), "+f"(c[2]), "+f"(c[3])
        : "r"(a0), "r"(a1), "r"(a2), "r"(a3), "r"(b0), "r"(b1));
}

// ---------------------------------------------------------------------------
// tf32 GEMM: C[M x 128] = A1 @ B1 (+ A2 @ B2) (+ bias)
// A*: [M x 128] row-major, B*: [128 x 128] row-major. Block tile 128x128,
// 256 threads (8 warps); warp w owns rows [16w,16w+16) x all 128 cols as
// 16 m16n8k8 tiles. BK=16 smem staging, pad-136 conflict-free frag reads.
// ---------------------------------------------------------------------------
__global__ void __launch_bounds__(256) gemm_tf32(
    const float* __restrict__ A1, const float* __restrict__ B1,
    const float* __restrict__ A2, const float* __restrict__ B2,
    const float* __restrict__ bias, float* __restrict__ C, int M)
{
    __shared__ uint32_t As[16][136];   // [k][m]
    __shared__ uint32_t Bs[16][136];   // [k][n]

    const int tid  = threadIdx.x;
    const int lane = tid & 31;
    const int warp = tid >> 5;
    const int g    = lane >> 2;    // 0..7
    const int tg   = lane & 3;     // 0..3
    const int m0   = blockIdx.x * 128;
    const int wr   = warp * 16;

    float acc[16][4];
#pragma unroll
    for (int j = 0; j < 16; j++)
#pragma unroll
        for (int i = 0; i < 4; i++) acc[j][i] = 0.f;

    // staging assignments
    const int ar = tid >> 1;          // A tile row 0..127
    const int ac = (tid & 1) * 8;     // A tile col base {0,8}
    const int br = tid >> 4;          // B tile row 0..15
    const int bc = (tid & 15) * 4;    // B tile col base 0..60

    const int a_row = min(m0 + ar, M - 1);   // clamp; stores are guarded

    const int nsrc = A2 ? 2 : 1;
    for (int s = 0; s < nsrc; s++) {
        const float* A = s ? A2 : A1;
        const float* B = s ? B2 : B1;
        for (int k0 = 0; k0 < 128; k0 += 16) {
            float4 av0 = *(const float4*)(A + (size_t)a_row * 128 + k0 + ac);
            float4 av1 = *(const float4*)(A + (size_t)a_row * 128 + k0 + ac + 4);
            float4 bv0 = *(const float4*)(B + (size_t)(k0 + br) * 128 + bc);
            float4 bv1 = *(const float4*)(B + (size_t)(k0 + br) * 128 + bc + 64);
            __syncthreads();
            As[ac + 0][ar] = f2tf(av0.x); As[ac + 1][ar] = f2tf(av0.y);
            As[ac + 2][ar] = f2tf(av0.z); As[ac + 3][ar] = f2tf(av0.w);
            As[ac + 4][ar] = f2tf(av1.x); As[ac + 5][ar] = f2tf(av1.y);
            As[ac + 6][ar] = f2tf(av1.z); As[ac + 7][ar] = f2tf(av1.w);
            Bs[br][bc + 0]  = f2tf(bv0.x); Bs[br][bc + 1]  = f2tf(bv0.y);
            Bs[br][bc + 2]  = f2tf(bv0.z); Bs[br][bc + 3]  = f2tf(bv0.w);
            Bs[br][bc + 64] = f2tf(bv1.x); Bs[br][bc + 65] = f2tf(bv1.y);
            Bs[br][bc + 66] = f2tf(bv1.z); Bs[br][bc + 67] = f2tf(bv1.w);
            __syncthreads();
#pragma unroll
            for (int kk = 0; kk < 16; kk += 8) {
                uint32_t a0 = As[kk + tg][wr + g];
                uint32_t a1 = As[kk + tg][wr + g + 8];
                uint32_t a2 = As[kk + tg + 4][wr + g];
                uint32_t a3 = As[kk + tg + 4][wr + g + 8];
#pragma unroll
                for (int j = 0; j < 16; j++) {
                    uint32_t b0 = Bs[kk + tg][8 * j + g];
                    uint32_t b1 = Bs[kk + tg + 4][8 * j + g];
                    mma_tf32(acc[j], a0, a1, a2, a3, b0, b1);
                }
            }
        }
    }

    // epilogue: c0=(g,2tg) c1=(g,2tg+1) c2=(g+8,2tg) c3=(g+8,2tg+1)
#pragma unroll
    for (int j = 0; j < 16; j++) {
        int col = 8 * j + 2 * tg;
        float bv0 = bias ? bias[col]     : 0.f;
        float bv1 = bias ? bias[col + 1] : 0.f;
        int r0 = m0 + wr + g;
        if (r0 < M) {
            float2 v = {acc[j][0] + bv0, acc[j][1] + bv1};
            *(float2*)(C + (size_t)r0 * 128 + col) = v;
        }
        int r1 = r0 + 8;
        if (r1 < M) {
            float2 v = {acc[j][2] + bv0, acc[j][3] + bv1};
            *(float2*)(C + (size_t)r1 * 128 + col) = v;
        }
    }
}

// ---------------------------------------------------------------------------
// row_ptr[n] = lower_bound(dst, n); dst sorted. rp[N] = E.
// ---------------------------------------------------------------------------
__global__ void rowptr_kernel(const int* __restrict__ dst, int n, int E)
{
    int t = blockIdx.x * blockDim.x + threadIdx.x;
    if (t > n) return;
    int lo = 0, hi = E;
    while (lo < hi) {
        int mid = (lo + hi) >> 1;
        if (dst[mid] < t) lo = mid + 1; else hi = mid;
    }
    g_rp[t] = lo;
}

// ---------------------------------------------------------------------------
// Per-edge score: sc[e] = sum_k w2[k] * tanh(pd[dst,k] + ps[src,k])
// (b1 folded into pd; b2 cancels in softmax.) Warp per edge, tanh.approx.
// ---------------------------------------------------------------------------
__device__ __forceinline__ float tanh_fast(float x) {
    float r;
    asm("tanh.approx.f32 %0, %1;" : "=f"(r) : "f"(x));
    return r;
}

__global__ void __launch_bounds__(256) score_kernel(
    const int* __restrict__ src, const int* __restrict__ dst,
    const float* __restrict__ w2, int E)
{
    int e    = (blockIdx.x * blockDim.x + threadIdx.x) >> 5;
    int lane = threadIdx.x & 31;
    if (e >= E) return;
    int d = dst[e], s = src[e];
    float4 a = ((const float4*)(g_pd + (size_t)d * F))[lane];
    float4 b = ((const float4*)(g_ps + (size_t)s * F))[lane];
    float4 w = ((const float4*)w2)[lane];
    float acc = w.x * tanh_fast(a.x + b.x)
              + w.y * tanh_fast(a.y + b.y)
              + w.z * tanh_fast(a.z + b.z)
              + w.w * tanh_fast(a.w + b.w);
#pragma unroll
    for (int o = 16; o; o >>= 1) acc += __shfl_xor_sync(0xffffffffu, acc, o);
    if (lane == 0) g_sc[e] = acc;
}

// ---------------------------------------------------------------------------
// Segmented softmax + weighted neighbor aggregation. Block(128) per node.
// ---------------------------------------------------------------------------
__global__ void __launch_bounds__(128) softagg_kernel(
    const float* __restrict__ feat, const int* __restrict__ src)
{
    int node = blockIdx.x;
    int tid  = threadIdx.x;
    int r0 = g_rp[node], r1 = g_rp[node + 1];
    __shared__ float red[4];

    float m = -3.402823466e38f;
    for (int e = r0 + tid; e < r1; e += 128) m = fmaxf(m, g_sc[e]);
#pragma unroll
    for (int o = 16; o; o >>= 1) m = fmaxf(m, __shfl_xor_sync(0xffffffffu, m, o));
    if ((tid & 31) == 0) red[tid >> 5] = m;
    __syncthreads();
    m = fmaxf(fmaxf(red[0], red[1]), fmaxf(red[2], red[3]));
    __syncthreads();

    float sum = 0.f;
    for (int e = r0 + tid; e < r1; e += 128) {
        float v = __expf(g_sc[e] - m);
        g_ex[e] = v;
        sum += v;
    }
#pragma unroll
    for (int o = 16; o; o >>= 1) sum += __shfl_xor_sync(0xffffffffu, sum, o);
    if ((tid & 31) == 0) red[tid >> 5] = sum;
    __syncthreads();
    sum = red[0] + red[1] + red[2] + red[3];
    float inv = (r1 > r0) ? (1.0f / sum) : 0.f;

    float acc = 0.f;
    for (int e = r0; e < r1; e++) {
        float w = g_ex[e];
        acc = fmaf(w, feat[(size_t)src[e] * F + tid], acc);
    }
    g_neigh[(size_t)node * F + tid] = acc * inv;
}

// ---------------------------------------------------------------------------
extern "C" void kernel_launch(void* const* d_in, const int* in_sizes, int n_in,
                              void* d_out, int out_size)
{
    const float* feat = (const float*)d_in[0];
    const int*   src  = (const int*)d_in[1];
    const int*   dst  = (const int*)d_in[2];
    const float* w1   = (const float*)d_in[3];
    const float* b1   = (const float*)d_in[4];
    const float* w2   = (const float*)d_in[5];
    // d_in[6] = b2: cancels in softmax, unused
    const float* wf   = (const float*)d_in[7];
    const float* bf   = (const float*)d_in[8];
    float* out = (float*)d_out;

    const int N = in_sizes[0] / F;   // 40000
    const int E = in_sizes[1];       // 640000

    float *pd, *ps, *neigh;
    cudaGetSymbolAddress((void**)&pd,    g_pd);
    cudaGetSymbolAddress((void**)&ps,    g_ps);
    cudaGetSymbolAddress((void**)&neigh, g_neigh);

    const int gblocks = (N + 127) / 128;   // 313

    // 1) proj_dst = feat @ w1[:F] + b1 ; proj_src = feat @ w1[F:]
    gemm_tf32<<<gblocks, 256>>>(feat, w1,         NULL, NULL, b1,   pd, N);
    gemm_tf32<<<gblocks, 256>>>(feat, w1 + F * F, NULL, NULL, NULL, ps, N);

    // 2) CSR row pointers over sorted dst
    rowptr_kernel<<<(N + 1 + 255) / 256, 256>>>(dst, N, E);

    // 3) per-edge attention scores
    score_kernel<<<(E + 7) / 8, 256>>>(src, dst, w2, E);

    // 4) segmented softmax + weighted aggregation
    softagg_kernel<<<N, 128>>>(feat, src);

    // 5) out = feat @ wf[:F] + neigh @ wf[F:] + bf  (fused dual-source GEMM)
    gemm_tf32<<<gblocks, 256>>>(feat, wf, neigh, wf + F * F, bf, out, N);
}

// round 3
// speedup vs baseline: 1.7284x; 1.1051x over previous
#include <cuda_runtime.h>
#include <cstddef>
#include <cstdint>

#define F 128
#define MAXN 40000
#define MAXE 640000

// Scratch (no cudaMalloc allowed): __device__ globals.
__device__ float g_pd[(size_t)MAXN * F];     // proj_dst + b1
__device__ float g_ps[(size_t)MAXN * F];     // proj_src
__device__ float g_ex[MAXE];                 // exp(score) per edge (max-free)
__device__ float g_neigh[(size_t)MAXN * F];  // attention-weighted neighborhood
__device__ int   g_rp[MAXN + 1];             // CSR row ptr over sorted dst

// ---------------------------------------------------------------------------
// tf32 helpers
// ---------------------------------------------------------------------------
__device__ __forceinline__ uint32_t f2tf(float x) {
    uint32_t r;
    asm("cvt.rna.tf32.f32 %0, %1;" : "=r"(r) : "f"(x));
    return r;
}

__device__ __forceinline__ void mma_tf32(float* c,
    uint32_t a0, uint32_t a1, uint32_t a2, uint32_t a3,
    uint32_t b0, uint32_t b1)
{
    asm("mma.sync.aligned.m16n8k8.row.col.f32.tf32.tf32.f32 "
        "{%0,%1,%2,%3}, {%4,%5,%6,%7}, {%8,%9}, {%0,%1,%2,%3};"
        : "+f"(c[0]), "+f"(c[1]), "+f"(c[2]), "+f"(c[3])
        : "r"(a0), "r"(a1), "r"(a2), "r"(a3), "r"(b0), "r"(b1));
}

__device__ __forceinline__ float tanh_fast(float x) {
    float r;
    asm("tanh.approx.f32 %0, %1;" : "=f"(r) : "f"(x));
    return r;
}

// ---------------------------------------------------------------------------
// tf32 GEMM: C[M x 128] = A1 @ B1 (+ A2 @ B2) (+ bias)
// Block tile 128x128, 256 threads (8 warps); warp w owns rows [16w,16w+16).
// ---------------------------------------------------------------------------
__global__ void __launch_bounds__(256) gemm_tf32(
    const float* __restrict__ A1, const float* __restrict__ B1,
    const float* __restrict__ A2, const float* __restrict__ B2,
    const float* __restrict__ bias, float* __restrict__ C, int M)
{
    __shared__ uint32_t As[16][136];   // [k][m]
    __shared__ uint32_t Bs[16][136];   // [k][n]

    const int tid  = threadIdx.x;
    const int lane = tid & 31;
    const int warp = tid >> 5;
    const int g    = lane >> 2;    // 0..7
    const int tg   = lane & 3;     // 0..3
    const int m0   = blockIdx.x * 128;
    const int wr   = warp * 16;

    float acc[16][4];
#pragma unroll
    for (int j = 0; j < 16; j++)
#pragma unroll
        for (int i = 0; i < 4; i++) acc[j][i] = 0.f;

    const int ar = tid >> 1;          // A tile row 0..127
    const int ac = (tid & 1) * 8;     // A tile col base {0,8}
    const int br = tid >> 4;          // B tile row 0..15
    const int bc = (tid & 15) * 4;    // B tile col base 0..60

    const int a_row = min(m0 + ar, M - 1);   // clamp; stores are guarded

    const int nsrc = A2 ? 2 : 1;
    for (int s = 0; s < nsrc; s++) {
        const float* A = s ? A2 : A1;
        const float* B = s ? B2 : B1;
        for (int k0 = 0; k0 < 128; k0 += 16) {
            float4 av0 = *(const float4*)(A + (size_t)a_row * 128 + k0 + ac);
            float4 av1 = *(const float4*)(A + (size_t)a_row * 128 + k0 + ac + 4);
            float4 bv0 = *(const float4*)(B + (size_t)(k0 + br) * 128 + bc);
            float4 bv1 = *(const float4*)(B + (size_t)(k0 + br) * 128 + bc + 64);
            __syncthreads();
            As[ac + 0][ar] = f2tf(av0.x); As[ac + 1][ar] = f2tf(av0.y);
            As[ac + 2][ar] = f2tf(av0.z); As[ac + 3][ar] = f2tf(av0.w);
            As[ac + 4][ar] = f2tf(av1.x); As[ac + 5][ar] = f2tf(av1.y);
            As[ac + 6][ar] = f2tf(av1.z); As[ac + 7][ar] = f2tf(av1.w);
            Bs[br][bc + 0]  = f2tf(bv0.x); Bs[br][bc + 1]  = f2tf(bv0.y);
            Bs[br][bc + 2]  = f2tf(bv0.z); Bs[br][bc + 3]  = f2tf(bv0.w);
            Bs[br][bc + 64] = f2tf(bv1.x); Bs[br][bc + 65] = f2tf(bv1.y);
            Bs[br][bc + 66] = f2tf(bv1.z); Bs[br][bc + 67] = f2tf(bv1.w);
            __syncthreads();
#pragma unroll
            for (int kk = 0; kk < 16; kk += 8) {
                uint32_t a0 = As[kk + tg][wr + g];
                uint32_t a1 = As[kk + tg][wr + g + 8];
                uint32_t a2 = As[kk + tg + 4][wr + g];
                uint32_t a3 = As[kk + tg + 4][wr + g + 8];
#pragma unroll
                for (int j = 0; j < 16; j++) {
                    uint32_t b0 = Bs[kk + tg][8 * j + g];
                    uint32_t b1 = Bs[kk + tg + 4][8 * j + g];
                    mma_tf32(acc[j], a0, a1, a2, a3, b0, b1);
                }
            }
        }
    }

#pragma unroll
    for (int j = 0; j < 16; j++) {
        int col = 8 * j + 2 * tg;
        float bv0 = bias ? bias[col]     : 0.f;
        float bv1 = bias ? bias[col + 1] : 0.f;
        int r0 = m0 + wr + g;
        if (r0 < M) {
            float2 v = {acc[j][0] + bv0, acc[j][1] + bv1};
            *(float2*)(C + (size_t)r0 * 128 + col) = v;
        }
        int r1 = r0 + 8;
        if (r1 < M) {
            float2 v = {acc[j][2] + bv0, acc[j][3] + bv1};
            *(float2*)(C + (size_t)r1 * 128 + col) = v;
        }
    }
}

// ---------------------------------------------------------------------------
// row_ptr[n] = lower_bound(dst, n); dst sorted. rp[N] = E.
// ---------------------------------------------------------------------------
__global__ void rowptr_kernel(const int* __restrict__ dst, int n, int E)
{
    int t = blockIdx.x * blockDim.x + threadIdx.x;
    if (t > n) return;
    int lo = 0, hi = E;
    while (lo < hi) {
        int mid = (lo + hi) >> 1;
        if (dst[mid] < t) lo = mid + 1; else hi = mid;
    }
    g_rp[t] = lo;
}

// ---------------------------------------------------------------------------
// Per-edge attention, max-free: g_ex[e] = exp(sum_k w2[k]*tanh(pd[n,k]+ps[src,k]))
// |score| <= ||w2||_1 (~9), so exp never overflows; max subtraction cancels in
// the softmax ratio and is dropped. b1 folded into pd, b2 cancels.
// One block (128 thr) per node: pd row + w2 held in registers (amortized over
// the node's edges). Each warp processes 4 edges at once: 8 lanes/edge,
// 16 features/lane => 3-shuffle reduction for 4 edges.
// ---------------------------------------------------------------------------
__global__ void __launch_bounds__(128) score_kernel(
    const int* __restrict__ src, const float* __restrict__ w2)
{
    const int node = blockIdx.x;
    const int tid  = threadIdx.x;
    const int warp = tid >> 5;
    const int lane = tid & 31;
    const int sub   = lane >> 3;   // which of 4 edges in the group
    const int chunk = lane & 7;    // which 16-feature slice

    const int r0 = g_rp[node], r1 = g_rp[node + 1];
    if (r0 == r1) return;

    __shared__ float spd[128], sw2[128];
    if (tid < 32) {
        ((float4*)spd)[tid] = ((const float4*)(g_pd + (size_t)node * F))[tid];
        ((float4*)sw2)[tid] = ((const float4*)w2)[tid];
    }
    __syncthreads();

    // lane's slice: features {i*32 + chunk*4 .. +3}, i = 0..3
    float4 pdv[4], wv[4];
#pragma unroll
    for (int i = 0; i < 4; i++) {
        pdv[i] = ((const float4*)spd)[i * 8 + chunk];
        wv[i]  = ((const float4*)sw2)[i * 8 + chunk];
    }

    for (int base = r0 + warp * 4; base < r1; base += 16) {
        int  e     = base + sub;
        bool valid = e < r1;
        int  s     = valid ? src[e] : src[r0];
        const float4* prow = (const float4*)(g_ps + (size_t)s * F);
        float acc = 0.f;
#pragma unroll
        for (int i = 0; i < 4; i++) {
            float4 b = prow[i * 8 + chunk];
            acc += wv[i].x * tanh_fast(pdv[i].x + b.x)
                 + wv[i].y * tanh_fast(pdv[i].y + b.y)
                 + wv[i].z * tanh_fast(pdv[i].z + b.z)
                 + wv[i].w * tanh_fast(pdv[i].w + b.w);
        }
        acc += __shfl_xor_sync(0xffffffffu, acc, 1);
        acc += __shfl_xor_sync(0xffffffffu, acc, 2);
        acc += __shfl_xor_sync(0xffffffffu, acc, 4);
        if (valid && chunk == 0) g_ex[e] = __expf(acc);
    }
}

// ---------------------------------------------------------------------------
// Fused denominator + weighted aggregation. Block(128) per node.
// neigh[n,k] = (sum_e ex[e] * feat[src[e],k]) / (sum_e ex[e])
// ---------------------------------------------------------------------------
__global__ void __launch_bounds__(128) sumagg_kernel(
    const float* __restrict__ feat, const int* __restrict__ src)
{
    const int node = blockIdx.x;
    const int tid  = threadIdx.x;
    const int r0 = g_rp[node], r1 = g_rp[node + 1];
    __shared__ float red[4];

    // denominator
    float s = 0.f;
    for (int e = r0 + tid; e < r1; e += 128) s += g_ex[e];
#pragma unroll
    for (int o = 16; o; o >>= 1) s += __shfl_xor_sync(0xffffffffu, s, o);
    if ((tid & 31) == 0) red[tid >> 5] = s;
    __syncthreads();
    s = red[0] + red[1] + red[2] + red[3];
    const float inv = (r1 > r0) ? (1.0f / s) : 0.f;

    // aggregation: thread tid owns feature tid; unroll x4 for MLP
    float acc = 0.f;
    int e = r0;
    for (; e + 4 <= r1; e += 4) {
        int   s0 = src[e],     s1 = src[e + 1], s2 = src[e + 2], s3 = src[e + 3];
        float w0 = g_ex[e],    w1 = g_ex[e + 1];
        float w2v = g_ex[e + 2], w3 = g_ex[e + 3];
        float v0 = feat[(size_t)s0 * F + tid];
        float v1 = feat[(size_t)s1 * F + tid];
        float v2 = feat[(size_t)s2 * F + tid];
        float v3 = feat[(size_t)s3 * F + tid];
        acc = fmaf(w0, v0, acc);
        acc = fmaf(w1, v1, acc);
        acc = fmaf(w2v, v2, acc);
        acc = fmaf(w3, v3, acc);
    }
    for (; e < r1; e++)
        acc = fmaf(g_ex[e], feat[(size_t)src[e] * F + tid], acc);

    g_neigh[(size_t)node * F + tid] = acc * inv;
}

// ---------------------------------------------------------------------------
extern "C" void kernel_launch(void* const* d_in, const int* in_sizes, int n_in,
                              void* d_out, int out_size)
{
    const float* feat = (const float*)d_in[0];
    const int*   src  = (const int*)d_in[1];
    const int*   dst  = (const int*)d_in[2];
    const float* w1   = (const float*)d_in[3];
    const float* b1   = (const float*)d_in[4];
    const float* w2   = (const float*)d_in[5];
    // d_in[6] = b2: cancels in softmax, unused
    const float* wf   = (const float*)d_in[7];
    const float* bf   = (const float*)d_in[8];
    float* out = (float*)d_out;

    const int N = in_sizes[0] / F;   // 40000
    const int E = in_sizes[1];       // 640000

    float *pd, *ps, *neigh;
    cudaGetSymbolAddress((void**)&pd,    g_pd);
    cudaGetSymbolAddress((void**)&ps,    g_ps);
    cudaGetSymbolAddress((void**)&neigh, g_neigh);

    const int gblocks = (N + 127) / 128;   // 313

    // 1) proj_dst = feat @ w1[:F] + b1 ; proj_src = feat @ w1[F:]
    gemm_tf32<<<gblocks, 256>>>(feat, w1,         NULL, NULL, b1,   pd, N);
    gemm_tf32<<<gblocks, 256>>>(feat, w1 + F * F, NULL, NULL, NULL, ps, N);

    // 2) CSR row pointers over sorted dst
    rowptr_kernel<<<(N + 1 + 255) / 256, 256>>>(dst, N, E);

    // 3) per-edge attention exp-scores (block per node, max-free)
    score_kernel<<<N, 128>>>(src, w2);

    // 4) fused denominator + weighted aggregation
    sumagg_kernel<<<N, 128>>>(feat, src);

    // 5) out = feat @ wf[:F] + neigh @ wf[F:] + bf  (fused dual-source GEMM)
    gemm_tf32<<<gblocks, 256>>>(feat, wf, neigh, wf + F * F, bf, out, N);
}

// round 4
// speedup vs baseline: 2.4026x; 1.3901x over previous
#include <cuda_runtime.h>
#include <cstddef>
#include <cstdint>

#define F 128
#define MAXN 40000
#define MAXE 640000

// Scratch (no cudaMalloc allowed): __device__ globals.
__device__ float g_pd[(size_t)MAXN * F];     // proj_dst + b1
__device__ float g_ps[(size_t)MAXN * F];     // proj_src
__device__ float g_neigh[(size_t)MAXN * F];  // attention-weighted neighborhood
__device__ int   g_rp[MAXN + 1];             // CSR row ptr over sorted dst

// ---------------------------------------------------------------------------
// tf32 helpers
// ---------------------------------------------------------------------------
__device__ __forceinline__ uint32_t f2tf(float x) {
    uint32_t r;
    asm("cvt.rna.tf32.f32 %0, %1;" : "=r"(r) : "f"(x));
    return r;
}

__device__ __forceinline__ void mma_tf32(float* c,
    uint32_t a0, uint32_t a1, uint32_t a2, uint32_t a3,
    uint32_t b0, uint32_t b1)
{
    asm("mma.sync.aligned.m16n8k8.row.col.f32.tf32.tf32.f32 "
        "{%0,%1,%2,%3}, {%4,%5,%6,%7}, {%8,%9}, {%0,%1,%2,%3};"
        : "+f"(c[0]), "+f"(c[1]), "+f"(c[2]), "+f"(c[3])
        : "r"(a0), "r"(a1), "r"(a2), "r"(a3), "r"(b0), "r"(b1));
}

__device__ __forceinline__ float tanh_fast(float x) {
    float r;
    asm("tanh.approx.f32 %0, %1;" : "=f"(r) : "f"(x));
    return r;
}

// ---------------------------------------------------------------------------
// tf32 GEMM: C[M x 128] = A1 @ B1 (+ A2 @ B2) (+ bias)
// Block tile 128x128, 256 threads (8 warps); warp w owns rows [16w,16w+16).
// ---------------------------------------------------------------------------
__global__ void __launch_bounds__(256) gemm_tf32(
    const float* __restrict__ A1, const float* __restrict__ B1,
    const float* __restrict__ A2, const float* __restrict__ B2,
    const float* __restrict__ bias, float* __restrict__ C, int M)
{
    __shared__ uint32_t As[16][136];   // [k][m]
    __shared__ uint32_t Bs[16][136];   // [k][n]

    const int tid  = threadIdx.x;
    const int lane = tid & 31;
    const int warp = tid >> 5;
    const int g    = lane >> 2;    // 0..7
    const int tg   = lane & 3;     // 0..3
    const int m0   = blockIdx.x * 128;
    const int wr   = warp * 16;

    float acc[16][4];
#pragma unroll
    for (int j = 0; j < 16; j++)
#pragma unroll
        for (int i = 0; i < 4; i++) acc[j][i] = 0.f;

    const int ar = tid >> 1;          // A tile row 0..127
    const int ac = (tid & 1) * 8;     // A tile col base {0,8}
    const int br = tid >> 4;          // B tile row 0..15
    const int bc = (tid & 15) * 4;    // B tile col base 0..60

    const int a_row = min(m0 + ar, M - 1);   // clamp; stores are guarded

    const int nsrc = A2 ? 2 : 1;
    for (int s = 0; s < nsrc; s++) {
        const float* A = s ? A2 : A1;
        const float* B = s ? B2 : B1;
        for (int k0 = 0; k0 < 128; k0 += 16) {
            float4 av0 = *(const float4*)(A + (size_t)a_row * 128 + k0 + ac);
            float4 av1 = *(const float4*)(A + (size_t)a_row * 128 + k0 + ac + 4);
            float4 bv0 = *(const float4*)(B + (size_t)(k0 + br) * 128 + bc);
            float4 bv1 = *(const float4*)(B + (size_t)(k0 + br) * 128 + bc + 64);
            __syncthreads();
            As[ac + 0][ar] = f2tf(av0.x); As[ac + 1][ar] = f2tf(av0.y);
            As[ac + 2][ar] = f2tf(av0.z); As[ac + 3][ar] = f2tf(av0.w);
            As[ac + 4][ar] = f2tf(av1.x); As[ac + 5][ar] = f2tf(av1.y);
            As[ac + 6][ar] = f2tf(av1.z); As[ac + 7][ar] = f2tf(av1.w);
            Bs[br][bc + 0]  = f2tf(bv0.x); Bs[br][bc + 1]  = f2tf(bv0.y);
            Bs[br][bc + 2]  = f2tf(bv0.z); Bs[br][bc + 3]  = f2tf(bv0.w);
            Bs[br][bc + 64] = f2tf(bv1.x); Bs[br][bc + 65] = f2tf(bv1.y);
            Bs[br][bc + 66] = f2tf(bv1.z); Bs[br][bc + 67] = f2tf(bv1.w);
            __syncthreads();
#pragma unroll
            for (int kk = 0; kk < 16; kk += 8) {
                uint32_t a0 = As[kk + tg][wr + g];
                uint32_t a1 = As[kk + tg][wr + g + 8];
                uint32_t a2 = As[kk + tg + 4][wr + g];
                uint32_t a3 = As[kk + tg + 4][wr + g + 8];
#pragma unroll
                for (int j = 0; j < 16; j++) {
                    uint32_t b0 = Bs[kk + tg][8 * j + g];
                    uint32_t b1 = Bs[kk + tg + 4][8 * j + g];
                    mma_tf32(acc[j], a0, a1, a2, a3, b0, b1);
                }
            }
        }
    }

#pragma unroll
    for (int j = 0; j < 16; j++) {
        int col = 8 * j + 2 * tg;
        float bv0 = bias ? bias[col]     : 0.f;
        float bv1 = bias ? bias[col + 1] : 0.f;
        int r0 = m0 + wr + g;
        if (r0 < M) {
            float2 v = {acc[j][0] + bv0, acc[j][1] + bv1};
            *(float2*)(C + (size_t)r0 * 128 + col) = v;
        }
        int r1 = r0 + 8;
        if (r1 < M) {
            float2 v = {acc[j][2] + bv0, acc[j][3] + bv1};
            *(float2*)(C + (size_t)r1 * 128 + col) = v;
        }
    }
}

// ---------------------------------------------------------------------------
// row_ptr[n] = lower_bound(dst, n); dst sorted. rp[N] = E.
// ---------------------------------------------------------------------------
__global__ void rowptr_kernel(const int* __restrict__ dst, int n, int E)
{
    int t = blockIdx.x * blockDim.x + threadIdx.x;
    if (t > n) return;
    int lo = 0, hi = E;
    while (lo < hi) {
        int mid = (lo + hi) >> 1;
        if (dst[mid] < t) lo = mid + 1; else hi = mid;
    }
    g_rp[t] = lo;
}

// ---------------------------------------------------------------------------
// Fully fused edge phase, max-free softmax. One WARP per node, lane owns
// features 4*lane..4*lane+3 of pd/w2/ps/feat/acc.
//   per edge: ex = exp(sum_k w2[k]*tanh(pd[n,k]+ps[src,k]))
//             den += ex ; acc += ex * feat[src]
//   neigh[n] = acc / den   (0 for zero-degree nodes)
// |score| <= ||w2||_1 (~9) so exp is overflow-safe without max subtraction;
// the max cancels in the ratio. b1 folded into pd; b2 cancels.
// Edges unrolled x2: independent load pairs + interleaved butterfly chains.
// ---------------------------------------------------------------------------
__global__ void __launch_bounds__(256) edge_fused_kernel(
    const float* __restrict__ feat, const int* __restrict__ src,
    const float* __restrict__ w2, int N)
{
    const int gw   = (blockIdx.x * blockDim.x + threadIdx.x) >> 5;
    const int lane = threadIdx.x & 31;
    if (gw >= N) return;
    const int node = gw;
    const int r0 = g_rp[node], r1 = g_rp[node + 1];

    const float4 pdv = ((const float4*)(g_pd + (size_t)node * F))[lane];
    const float4 wv  = ((const float4*)w2)[lane];

    float4 acc = {0.f, 0.f, 0.f, 0.f};
    float  den = 0.f;

    int e = r0;
    for (; e + 2 <= r1; e += 2) {
        int s0 = __ldg(src + e);
        int s1 = __ldg(src + e + 1);
        float4 p0 = ((const float4*)(g_ps + (size_t)s0 * F))[lane];
        float4 p1 = ((const float4*)(g_ps + (size_t)s1 * F))[lane];
        float4 f0 = ((const float4*)(feat + (size_t)s0 * F))[lane];
        float4 f1 = ((const float4*)(feat + (size_t)s1 * F))[lane];

        float sc0 = wv.x * tanh_fast(pdv.x + p0.x)
                  + wv.y * tanh_fast(pdv.y + p0.y)
                  + wv.z * tanh_fast(pdv.z + p0.z)
                  + wv.w * tanh_fast(pdv.w + p0.w);
        float sc1 = wv.x * tanh_fast(pdv.x + p1.x)
                  + wv.y * tanh_fast(pdv.y + p1.y)
                  + wv.z * tanh_fast(pdv.z + p1.z)
                  + wv.w * tanh_fast(pdv.w + p1.w);
#pragma unroll
        for (int o = 16; o; o >>= 1) {
            sc0 += __shfl_xor_sync(0xffffffffu, sc0, o);
            sc1 += __shfl_xor_sync(0xffffffffu, sc1, o);
        }
        float ex0 = __expf(sc0);
        float ex1 = __expf(sc1);
        den += ex0 + ex1;
        acc.x = fmaf(ex0, f0.x, acc.x); acc.x = fmaf(ex1, f1.x, acc.x);
        acc.y = fmaf(ex0, f0.y, acc.y); acc.y = fmaf(ex1, f1.y, acc.y);
        acc.z = fmaf(ex0, f0.z, acc.z); acc.z = fmaf(ex1, f1.z, acc.z);
        acc.w = fmaf(ex0, f0.w, acc.w); acc.w = fmaf(ex1, f1.w, acc.w);
    }
    if (e < r1) {
        int s0 = __ldg(src + e);
        float4 p0 = ((const float4*)(g_ps + (size_t)s0 * F))[lane];
        float4 f0 = ((const float4*)(feat + (size_t)s0 * F))[lane];
        float sc0 = wv.x * tanh_fast(pdv.x + p0.x)
                  + wv.y * tanh_fast(pdv.y + p0.y)
                  + wv.z * tanh_fast(pdv.z + p0.z)
                  + wv.w * tanh_fast(pdv.w + p0.w);
#pragma unroll
        for (int o = 16; o; o >>= 1) sc0 += __shfl_xor_sync(0xffffffffu, sc0, o);
        float ex0 = __expf(sc0);
        den += ex0;
        acc.x = fmaf(ex0, f0.x, acc.x);
        acc.y = fmaf(ex0, f0.y, acc.y);
        acc.z = fmaf(ex0, f0.z, acc.z);
        acc.w = fmaf(ex0, f0.w, acc.w);
    }

    const float inv = (r1 > r0) ? (1.0f / den) : 0.f;
    float4 outv = {acc.x * inv, acc.y * inv, acc.z * inv, acc.w * inv};
    ((float4*)(g_neigh + (size_t)node * F))[lane] = outv;
}

// ---------------------------------------------------------------------------
extern "C" void kernel_launch(void* const* d_in, const int* in_sizes, int n_in,
                              void* d_out, int out_size)
{
    const float* feat = (const float*)d_in[0];
    const int*   src  = (const int*)d_in[1];
    const int*   dst  = (const int*)d_in[2];
    const float* w1   = (const float*)d_in[3];
    const float* b1   = (const float*)d_in[4];
    const float* w2   = (const float*)d_in[5];
    // d_in[6] = b2: cancels in softmax, unused
    const float* wf   = (const float*)d_in[7];
    const float* bf   = (const float*)d_in[8];
    float* out = (float*)d_out;

    const int N = in_sizes[0] / F;   // 40000
    const int E = in_sizes[1];       // 640000

    float *pd, *ps, *neigh;
    cudaGetSymbolAddress((void**)&pd,    g_pd);
    cudaGetSymbolAddress((void**)&ps,    g_ps);
    cudaGetSymbolAddress((void**)&neigh, g_neigh);

    const int gblocks = (N + 127) / 128;   // 313

    // 1) proj_dst = feat @ w1[:F] + b1 ; proj_src = feat @ w1[F:]
    gemm_tf32<<<gblocks, 256>>>(feat, w1,         NULL, NULL, b1,   pd, N);
    gemm_tf32<<<gblocks, 256>>>(feat, w1 + F * F, NULL, NULL, NULL, ps, N);

    // 2) CSR row pointers over sorted dst
    rowptr_kernel<<<(N + 1 + 255) / 256, 256>>>(dst, N, E);

    // 3) fused: scores + exp + denominator + weighted aggregation
    edge_fused_kernel<<<(N * 32 + 255) / 256, 256>>>(feat, src, w2, N);

    // 4) out = feat @ wf[:F] + neigh @ wf[F:] + bf  (fused dual-source GEMM)
    gemm_tf32<<<gblocks, 256>>>(feat, wf, neigh, wf + F * F, bf, out, N);
}

// round 6
// speedup vs baseline: 2.9876x; 1.2435x over previous
#include <cuda_runtime.h>
#include <cstddef>
#include <cstdint>

#define F 128
#define MAXN 40000
#define MAXE 640000

// Scratch (no cudaMalloc allowed): __device__ globals.
__device__ float g_pd[(size_t)MAXN * F];     // proj_dst + b1
__device__ float g_ps[(size_t)MAXN * F];     // proj_src
__device__ float g_neigh[(size_t)MAXN * F];  // attention-weighted neighborhood
__device__ int   g_rp[MAXN + 1];             // CSR row ptr over sorted dst

// ---------------------------------------------------------------------------
// tf32 helpers
// ---------------------------------------------------------------------------
__device__ __forceinline__ uint32_t f2tf(float x) {
    uint32_t r;
    asm("cvt.rna.tf32.f32 %0, %1;" : "=r"(r) : "f"(x));
    return r;
}

__device__ __forceinline__ void mma_tf32(float* c,
    uint32_t a0, uint32_t a1, uint32_t a2, uint32_t a3,
    uint32_t b0, uint32_t b1)
{
    asm("mma.sync.aligned.m16n8k8.row.col.f32.tf32.tf32.f32 "
        "{%0,%1,%2,%3}, {%4,%5,%6,%7}, {%8,%9}, {%0,%1,%2,%3};"
        : "+f"(c[0]), "+f"(c[1]), "+f"(c[2]), "+f"(c[3])
        : "r"(a0), "r"(a1), "r"(a2), "r"(a3), "r"(b0), "r"(b1));
}

__device__ __forceinline__ float tanh_fast(float x) {
    float r;
    asm("tanh.approx.f32 %0, %1;" : "=f"(r) : "f"(x));
    return r;
}

// ---------------------------------------------------------------------------
// tf32 GEMM, double-buffered. Grid (blocks_m, ysel).
//   ysel==0: C_a[M x 128] = A1 @ B1a (+ A2 @ B2 if A2) (+ bias_a)
//   ysel==1: C_b[M x 128] = A1 @ B1b (+ bias_b)          [proj-pair fusion]
// A*: [M x 128] row-major fp32; B*: [128 x 128] row-major fp32 (k rows).
// Block tile 128x128, 256 threads, 8 warps in 4x2; warp tile m32 x n64.
// Stage k+1 global loads are issued before stage k MMAs (latency overlap).
// ---------------------------------------------------------------------------
__global__ void __launch_bounds__(256) gemm_tf32(
    const float* __restrict__ A1,
    const float* __restrict__ B1a, const float* __restrict__ B1b,
    const float* __restrict__ A2,  const float* __restrict__ B2,
    const float* __restrict__ bias_a, const float* __restrict__ bias_b,
    float* __restrict__ Ca, float* __restrict__ Cb, int M)
{
    __shared__ uint32_t As[2][16][136];   // [buf][k][m]
    __shared__ uint32_t Bs[2][16][136];   // [buf][k][n]

    const int tid  = threadIdx.x;
    const int lane = tid & 31;
    const int warp = tid >> 5;
    const int g    = lane >> 2;    // 0..7
    const int tg   = lane & 3;     // 0..3
    const int m0   = blockIdx.x * 128;
    const int wr   = (warp & 3) * 32;   // warp row base
    const int wc   = (warp >> 2) * 64;  // warp col base

    const float* B1   = blockIdx.y ? B1b : B1a;
    const float* bias = blockIdx.y ? bias_b : bias_a;
    float*       C    = blockIdx.y ? Cb : Ca;
    const int nsrc = (blockIdx.y == 0 && A2) ? 2 : 1;
    const int nst  = nsrc * 8;

    float acc[2][8][4];
#pragma unroll
    for (int mt = 0; mt < 2; mt++)
#pragma unroll
        for (int j = 0; j < 8; j++)
#pragma unroll
            for (int i = 0; i < 4; i++) acc[mt][j][i] = 0.f;

    const int ar = tid >> 1;          // A tile row 0..127
    const int ac = (tid & 1) * 8;     // A tile col base {0,8}
    const int br = tid >> 4;          // B tile row 0..15
    const int bc = (tid & 15) * 4;    // B tile col base 0..60
    const int arow = min(m0 + ar, M - 1);   // clamp; stores guarded

    float4 av0, av1, bv0, bv1;

    auto loadst = [&](int st) {
        const float* A = (st >= 8) ? A2 : A1;
        const float* B = (st >= 8) ? B2 : B1;
        const int k0 = (st & 7) * 16;
        av0 = *(const float4*)(A + (size_t)arow * 128 + k0 + ac);
        av1 = *(const float4*)(A + (size_t)arow * 128 + k0 + ac + 4);
        bv0 = *(const float4*)(B + (size_t)(k0 + br) * 128 + bc);
        bv1 = *(const float4*)(B + (size_t)(k0 + br) * 128 + bc + 64);
    };
    auto storest = [&](int b) {
        As[b][ac + 0][ar] = f2tf(av0.x); As[b][ac + 1][ar] = f2tf(av0.y);
        As[b][ac + 2][ar] = f2tf(av0.z); As[b][ac + 3][ar] = f2tf(av0.w);
        As[b][ac + 4][ar] = f2tf(av1.x); As[b][ac + 5][ar] = f2tf(av1.y);
        As[b][ac + 6][ar] = f2tf(av1.z); As[b][ac + 7][ar] = f2tf(av1.w);
        Bs[b][br][bc + 0]  = f2tf(bv0.x); Bs[b][br][bc + 1]  = f2tf(bv0.y);
        Bs[b][br][bc + 2]  = f2tf(bv0.z); Bs[b][br][bc + 3]  = f2tf(bv0.w);
        Bs[b][br][bc + 64] = f2tf(bv1.x); Bs[b][br][bc + 65] = f2tf(bv1.y);
        Bs[b][br][bc + 66] = f2tf(bv1.z); Bs[b][br][bc + 67] = f2tf(bv1.w);
    };

    loadst(0);
    storest(0);
    __syncthreads();

    for (int st = 0; st < nst; st++) {
        const int b = st & 1;
        if (st + 1 < nst) loadst(st + 1);   // prefetch next stage (global)
#pragma unroll
        for (int kk = 0; kk < 16; kk += 8) {
            uint32_t a[2][4];
#pragma unroll
            for (int mt = 0; mt < 2; mt++) {
                int rb = wr + mt * 16;
                a[mt][0] = As[b][kk + tg][rb + g];
                a[mt][1] = As[b][kk + tg][rb + g + 8];
                a[mt][2] = As[b][kk + tg + 4][rb + g];
                a[mt][3] = As[b][kk + tg + 4][rb + g + 8];
            }
#pragma unroll
            for (int j = 0; j < 8; j++) {
                uint32_t b0 = Bs[b][kk + tg][wc + 8 * j + g];
                uint32_t b1 = Bs[b][kk + tg + 4][wc + 8 * j + g];
                mma_tf32(acc[0][j], a[0][0], a[0][1], a[0][2], a[0][3], b0, b1);
                mma_tf32(acc[1][j], a[1][0], a[1][1], a[1][2], a[1][3], b0, b1);
            }
        }
        __syncthreads();
        if (st + 1 < nst) {
            storest(b ^ 1);
            __syncthreads();
        }
    }

    // epilogue: frag c0=(g,2tg) c1=(g,2tg+1) c2=(g+8,2tg) c3=(g+8,2tg+1)
#pragma unroll
    for (int mt = 0; mt < 2; mt++) {
#pragma unroll
        for (int j = 0; j < 8; j++) {
            int col = wc + 8 * j + 2 * tg;
            float bv_0 = bias ? bias[col]     : 0.f;
            float bv_1 = bias ? bias[col + 1] : 0.f;
            int r0 = m0 + wr + 16 * mt + g;
            if (r0 < M) {
                float2 v = {acc[mt][j][0] + bv_0, acc[mt][j][1] + bv_1};
                *(float2*)(C + (size_t)r0 * 128 + col) = v;
            }
            int r1 = r0 + 8;
            if (r1 < M) {
                float2 v = {acc[mt][j][2] + bv_0, acc[mt][j][3] + bv_1};
                *(float2*)(C + (size_t)r1 * 128 + col) = v;
            }
        }
    }
}

// ---------------------------------------------------------------------------
// row_ptr[n] = lower_bound(dst, n); dst sorted. rp[N] = E.
// ---------------------------------------------------------------------------
__global__ void rowptr_kernel(const int* __restrict__ dst, int n, int E)
{
    int t = blockIdx.x * blockDim.x + threadIdx.x;
    if (t > n) return;
    int lo = 0, hi = E;
    while (lo < hi) {
        int mid = (lo + hi) >> 1;
        if (dst[mid] < t) lo = mid + 1; else hi = mid;
    }
    g_rp[t] = lo;
}

// ---------------------------------------------------------------------------
// Fully fused edge phase, max-free softmax. One WARP per node, lane owns
// features 4*lane..4*lane+3 of pd/w2/ps/feat/acc.
//   per edge: ex = exp(sum_k w2[k]*tanh(pd[n,k]+ps[src,k]))
//             den += ex ; acc += ex * feat[src]
//   neigh[n] = acc / den   (0 for zero-degree nodes)
// |score| <= ||w2||_1 (~9) so exp is overflow-safe without max subtraction;
// the max cancels in the ratio. b1 folded into pd; b2 cancels.
// ---------------------------------------------------------------------------
__global__ void __launch_bounds__(256) edge_fused_kernel(
    const float* __restrict__ feat, const int* __restrict__ src,
    const float* __restrict__ w2, int N)
{
    const int gw   = (blockIdx.x * blockDim.x + threadIdx.x) >> 5;
    const int lane = threadIdx.x & 31;
    if (gw >= N) return;
    const int node = gw;
    const int r0 = g_rp[node], r1 = g_rp[node + 1];

    const float4 pdv = ((const float4*)(g_pd + (size_t)node * F))[lane];
    const float4 wv  = ((const float4*)w2)[lane];

    float4 acc = {0.f, 0.f, 0.f, 0.f};
    float  den = 0.f;

    int e = r0;
    for (; e + 2 <= r1; e += 2) {
        int s0 = __ldg(src + e);
        int s1 = __ldg(src + e + 1);
        float4 p0 = ((const float4*)(g_ps + (size_t)s0 * F))[lane];
        float4 p1 = ((const float4*)(g_ps + (size_t)s1 * F))[lane];
        float4 f0 = ((const float4*)(feat + (size_t)s0 * F))[lane];
        float4 f1 = ((const float4*)(feat + (size_t)s1 * F))[lane];

        float sc0 = wv.x * tanh_fast(pdv.x + p0.x)
                  + wv.y * tanh_fast(pdv.y + p0.y)
                  + wv.z * tanh_fast(pdv.z + p0.z)
                  + wv.w * tanh_fast(pdv.w + p0.w);
        float sc1 = wv.x * tanh_fast(pdv.x + p1.x)
                  + wv.y * tanh_fast(pdv.y + p1.y)
                  + wv.z * tanh_fast(pdv.z + p1.z)
                  + wv.w * tanh_fast(pdv.w + p1.w);
#pragma unroll
        for (int o = 16; o; o >>= 1) {
            sc0 += __shfl_xor_sync(0xffffffffu, sc0, o);
            sc1 += __shfl_xor_sync(0xffffffffu, sc1, o);
        }
        float ex0 = __expf(sc0);
        float ex1 = __expf(sc1);
        den += ex0 + ex1;
        acc.x = fmaf(ex0, f0.x, acc.x); acc.x = fmaf(ex1, f1.x, acc.x);
        acc.y = fmaf(ex0, f0.y, acc.y); acc.y = fmaf(ex1, f1.y, acc.y);
        acc.z = fmaf(ex0, f0.z, acc.z); acc.z = fmaf(ex1, f1.z, acc.z);
        acc.w = fmaf(ex0, f0.w, acc.w); acc.w = fmaf(ex1, f1.w, acc.w);
    }
    if (e < r1) {
        int s0 = __ldg(src + e);
        float4 p0 = ((const float4*)(g_ps + (size_t)s0 * F))[lane];
        float4 f0 = ((const float4*)(feat + (size_t)s0 * F))[lane];
        float sc0 = wv.x * tanh_fast(pdv.x + p0.x)
                  + wv.y * tanh_fast(pdv.y + p0.y)
                  + wv.z * tanh_fast(pdv.z + p0.z)
                  + wv.w * tanh_fast(pdv.w + p0.w);
#pragma unroll
        for (int o = 16; o; o >>= 1) sc0 += __shfl_xor_sync(0xffffffffu, sc0, o);
        float ex0 = __expf(sc0);
        den += ex0;
        acc.x = fmaf(ex0, f0.x, acc.x);
        acc.y = fmaf(ex0, f0.y, acc.y);
        acc.z = fmaf(ex0, f0.z, acc.z);
        acc.w = fmaf(ex0, f0.w, acc.w);
    }

    const float inv = (r1 > r0) ? (1.0f / den) : 0.f;
    float4 outv = {acc.x * inv, acc.y * inv, acc.z * inv, acc.w * inv};
    ((float4*)(g_neigh + (size_t)node * F))[lane] = outv;
}

// ---------------------------------------------------------------------------
extern "C" void kernel_launch(void* const* d_in, const int* in_sizes, int n_in,
                              void* d_out, int out_size)
{
    const float* feat = (const float*)d_in[0];
    const int*   src  = (const int*)d_in[1];
    const int*   dst  = (const int*)d_in[2];
    const float* w1   = (const float*)d_in[3];
    const float* b1   = (const float*)d_in[4];
    const float* w2   = (const float*)d_in[5];
    // d_in[6] = b2: cancels in softmax, unused
    const float* wf   = (const float*)d_in[7];
    const float* bf   = (const float*)d_in[8];
    float* out = (float*)d_out;

    const int N = in_sizes[0] / F;   // 40000
    const int E = in_sizes[1];       // 640000

    float *pd, *ps, *neigh;
    cudaGetSymbolAddress((void**)&pd,    g_pd);
    cudaGetSymbolAddress((void**)&ps,    g_ps);
    cudaGetSymbolAddress((void**)&neigh, g_neigh);

    const int gblocks = (N + 127) / 128;   // 313

    // 1) fused pair: pd = feat @ w1[:F] + b1 ; ps = feat @ w1[F:]
    gemm_tf32<<<dim3(gblocks, 2), 256>>>(feat, w1, w1 + F * F, NULL, NULL,
                                         b1, NULL, pd, ps, N);

    // 2) CSR row pointers over sorted dst
    rowptr_kernel<<<(N + 1 + 255) / 256, 256>>>(dst, N, E);

    // 3) fused: scores + exp + denominator + weighted aggregation
    edge_fused_kernel<<<(N * 32 + 255) / 256, 256>>>(feat, src, w2, N);

    // 4) out = feat @ wf[:F] + neigh @ wf[F:] + bf  (dual-source GEMM)
    gemm_tf32<<<dim3(gblocks, 1), 256>>>(feat, wf, NULL, neigh, wf + F * F,
                                         bf, NULL, out, NULL, N);
}

// round 7
// speedup vs baseline: 3.0214x; 1.0113x over previous
#include <cuda_runtime.h>
#include <cstddef>
#include <cstdint>

#define F 128
#define MAXN 40000
#define MAXE 640000

// Scratch (no cudaMalloc allowed): __device__ globals.
__device__ float    g_pd[(size_t)MAXN * F];    // proj_dst + b1 (fp32)
__device__ float    g_ps[(size_t)MAXN * F];    // proj_src (fp32)
__device__ uint32_t g_ft[(size_t)MAXN * F];    // feat pre-converted to tf32
__device__ uint32_t g_nt[(size_t)MAXN * F];    // neigh in tf32 (edge output)
__device__ uint32_t g_w1t[2 * F * F];          // w1 tf32
__device__ uint32_t g_wft[2 * F * F];          // wf tf32
__device__ int      g_rp[MAXN + 1];            // CSR row ptr over sorted dst

// ---------------------------------------------------------------------------
// helpers
// ---------------------------------------------------------------------------
__device__ __forceinline__ uint32_t f2tf(float x) {
    uint32_t r;
    asm("cvt.rna.tf32.f32 %0, %1;" : "=r"(r) : "f"(x));
    return r;
}
__device__ __forceinline__ void mma_tf32(float* c,
    uint32_t a0, uint32_t a1, uint32_t a2, uint32_t a3,
    uint32_t b0, uint32_t b1)
{
    asm("mma.sync.aligned.m16n8k8.row.col.f32.tf32.tf32.f32 "
        "{%0,%1,%2,%3}, {%4,%5,%6,%7}, {%8,%9}, {%0,%1,%2,%3};"
        : "+f"(c[0]), "+f"(c[1]), "+f"(c[2]), "+f"(c[3])
        : "r"(a0), "r"(a1), "r"(a2), "r"(a3), "r"(b0), "r"(b1));
}
__device__ __forceinline__ float tanh_fast(float x) {
    float r;
    asm("tanh.approx.f32 %0, %1;" : "=f"(r) : "f"(x));
    return r;
}
#define CP16(dst, src) \
    asm volatile("cp.async.cg.shared.global [%0], [%1], 16;" :: "r"(dst), "l"(src))
#define CP_COMMIT() asm volatile("cp.async.commit_group;" ::: "memory")
#define CP_WAIT1()  asm volatile("cp.async.wait_group 1;" ::: "memory")

// ---------------------------------------------------------------------------
// elementwise fp32 -> tf32 (RNA), vectorized x4
// ---------------------------------------------------------------------------
__global__ void conv_tf32(const float* __restrict__ x, uint32_t* __restrict__ y,
                          int n4)
{
    int i = blockIdx.x * blockDim.x + threadIdx.x;
    if (i >= n4) return;
    float4 v = ((const float4*)x)[i];
    uint4 o = {f2tf(v.x), f2tf(v.y), f2tf(v.z), f2tf(v.w)};
    ((uint4*)y)[i] = o;
}

// ---------------------------------------------------------------------------
// tf32 GEMM, 3-stage cp.async pipeline. Grid (blocks_m, ysel).
//   ysel==0: Ca = A1 @ B1a (+ A2 @ B2 if A2) (+ bias_a)
//   ysel==1: Cb = A1 @ B1b (+ bias_b)
// A*: [M x 128] tf32 row-major; B*: [128 x 128] tf32 row-major (k rows).
// Block tile 128x128, 256 threads, 8 warps 4x2; warp tile m32 x n64; BK=16.
// smem: A [m][k] stride 20 (pad), B [k][n] stride 136 (pad) — both
// conflict-free for the m16n8k8 fragment pattern.
// ---------------------------------------------------------------------------
#define A_STW 20
#define B_STW 136
#define A_STAGE_W (128 * A_STW)          // 2560 words
#define B_STAGE_W (16 * B_STW)           // 2176 words
#define GEMM_SMEM ((3 * A_STAGE_W + 3 * B_STAGE_W) * 4)   // 56832 B

__global__ void __launch_bounds__(256) gemm_tf32(
    const uint32_t* __restrict__ A1,
    const uint32_t* __restrict__ B1a, const uint32_t* __restrict__ B1b,
    const uint32_t* __restrict__ A2,  const uint32_t* __restrict__ B2,
    const float* __restrict__ bias_a, const float* __restrict__ bias_b,
    float* __restrict__ Ca, float* __restrict__ Cb, int M)
{
    extern __shared__ uint32_t smw[];
    uint32_t* sA = smw;                       // 3 stages A
    uint32_t* sB = smw + 3 * A_STAGE_W;       // 3 stages B

    const int tid  = threadIdx.x;
    const int lane = tid & 31;
    const int warp = tid >> 5;
    const int g    = lane >> 2;
    const int tg   = lane & 3;
    const int m0   = blockIdx.x * 128;
    const int wr   = (warp & 3) * 32;
    const int wc   = (warp >> 2) * 64;

    const uint32_t* B1 = blockIdx.y ? B1b : B1a;
    const float* bias  = blockIdx.y ? bias_b : bias_a;
    float*       C     = blockIdx.y ? Cb : Ca;
    const int nst = (blockIdx.y == 0 && A2) ? 16 : 8;

    // cp.async chunk assignments (2 A-chunks + 2 B-chunks per thread)
    const int a_row0 = tid >> 2;               // 0..63
    const int a_kc   = (tid & 3) * 4;          // word offset in row
    const int b_row0 = tid >> 5;               // 0..7
    const int b_nc   = (tid & 31) * 4;
    const int ar0 = min(m0 + a_row0,      M - 1);
    const int ar1 = min(m0 + a_row0 + 64, M - 1);

    const uint32_t sA_b = (uint32_t)__cvta_generic_to_shared(sA);
    const uint32_t sB_b = (uint32_t)__cvta_generic_to_shared(sB);

    auto issue_stage = [&](int st, int buf) {
        const uint32_t* A = (st >= 8) ? A2 : A1;
        const uint32_t* B = (st >= 8) ? B2 : B1;
        const int k0 = (st & 7) * 16;
        CP16(sA_b + (buf * A_STAGE_W + a_row0 * A_STW + a_kc) * 4,
             A + (size_t)ar0 * 128 + k0 + a_kc);
        CP16(sA_b + (buf * A_STAGE_W + (a_row0 + 64) * A_STW + a_kc) * 4,
             A + (size_t)ar1 * 128 + k0 + a_kc);
        CP16(sB_b + (buf * B_STAGE_W + b_row0 * B_STW + b_nc) * 4,
             B + (size_t)(k0 + b_row0) * 128 + b_nc);
        CP16(sB_b + (buf * B_STAGE_W + (b_row0 + 8) * B_STW + b_nc) * 4,
             B + (size_t)(k0 + b_row0 + 8) * 128 + b_nc);
        CP_COMMIT();
    };

    float acc[2][8][4];
#pragma unroll
    for (int mt = 0; mt < 2; mt++)
#pragma unroll
        for (int j = 0; j < 8; j++)
#pragma unroll
            for (int i = 0; i < 4; i++) acc[mt][j][i] = 0.f;

    issue_stage(0, 0);
    issue_stage(1, 1);

    for (int st = 0; st < nst; st++) {
        const int buf = st % 3;
        CP_WAIT1();
        __syncthreads();
        if (st + 2 < nst) issue_stage(st + 2, (st + 2) % 3);

        const uint32_t* Ab = sA + buf * A_STAGE_W;
        const uint32_t* Bb = sB + buf * B_STAGE_W;
#pragma unroll
        for (int kk = 0; kk < 16; kk += 8) {
            uint32_t a[2][4];
#pragma unroll
            for (int mt = 0; mt < 2; mt++) {
                const uint32_t* r0 = Ab + (wr + mt * 16 + g) * A_STW + kk + tg;
                const uint32_t* r1 = r0 + 8 * A_STW;
                a[mt][0] = r0[0];
                a[mt][1] = r1[0];
                a[mt][2] = r0[4];
                a[mt][3] = r1[4];
            }
#pragma unroll
            for (int j = 0; j < 8; j++) {
                uint32_t b0 = Bb[(kk + tg) * B_STW + wc + 8 * j + g];
                uint32_t b1 = Bb[(kk + tg + 4) * B_STW + wc + 8 * j + g];
                mma_tf32(acc[0][j], a[0][0], a[0][1], a[0][2], a[0][3], b0, b1);
                mma_tf32(acc[1][j], a[1][0], a[1][1], a[1][2], a[1][3], b0, b1);
            }
        }
        __syncthreads();
    }

    // epilogue: frag c0=(g,2tg) c1=(g,2tg+1) c2=(g+8,2tg) c3=(g+8,2tg+1)
#pragma unroll
    for (int mt = 0; mt < 2; mt++) {
#pragma unroll
        for (int j = 0; j < 8; j++) {
            int col = wc + 8 * j + 2 * tg;
            float bv0 = bias ? bias[col]     : 0.f;
            float bv1 = bias ? bias[col + 1] : 0.f;
            int r0 = m0 + wr + 16 * mt + g;
            if (r0 < M) {
                float2 v = {acc[mt][j][0] + bv0, acc[mt][j][1] + bv1};
                *(float2*)(C + (size_t)r0 * 128 + col) = v;
            }
            int r1 = r0 + 8;
            if (r1 < M) {
                float2 v = {acc[mt][j][2] + bv0, acc[mt][j][3] + bv1};
                *(float2*)(C + (size_t)r1 * 128 + col) = v;
            }
        }
    }
}

// ---------------------------------------------------------------------------
// row_ptr[n] = lower_bound(dst, n); dst sorted. rp[N] = E.
// ---------------------------------------------------------------------------
__global__ void rowptr_kernel(const int* __restrict__ dst, int n, int E)
{
    int t = blockIdx.x * blockDim.x + threadIdx.x;
    if (t > n) return;
    int lo = 0, hi = E;
    while (lo < hi) {
        int mid = (lo + hi) >> 1;
        if (dst[mid] < t) lo = mid + 1; else hi = mid;
    }
    g_rp[t] = lo;
}

// ---------------------------------------------------------------------------
// Fused edge phase, max-free softmax. One WARP per node; lane owns feats
// 4l..4l+3. Writes neigh as tf32 for the final GEMM.
//   per edge: ex = exp(sum_k w2[k]*tanh(pd[n,k]+ps[src,k]))
//             den += ex ; acc += ex * feat[src]
// |score| <= ||w2||_1 (~9): exp overflow-safe; max cancels in the ratio.
// b1 folded into pd; b2 cancels in softmax.
// ---------------------------------------------------------------------------
__global__ void __launch_bounds__(256) edge_fused_kernel(
    const float* __restrict__ feat, const int* __restrict__ src,
    const float* __restrict__ w2, int N)
{
    const int gw   = (blockIdx.x * blockDim.x + threadIdx.x) >> 5;
    const int lane = threadIdx.x & 31;
    if (gw >= N) return;
    const int node = gw;
    const int r0 = g_rp[node], r1 = g_rp[node + 1];

    const float4 pdv = ((const float4*)(g_pd + (size_t)node * F))[lane];
    const float4 wv  = ((const float4*)w2)[lane];

    float4 acc = {0.f, 0.f, 0.f, 0.f};
    float  den = 0.f;

    int e = r0;
    for (; e + 2 <= r1; e += 2) {
        int s0 = __ldg(src + e);
        int s1 = __ldg(src + e + 1);
        float4 p0 = ((const float4*)(g_ps + (size_t)s0 * F))[lane];
        float4 p1 = ((const float4*)(g_ps + (size_t)s1 * F))[lane];
        float4 f0 = ((const float4*)(feat + (size_t)s0 * F))[lane];
        float4 f1 = ((const float4*)(feat + (size_t)s1 * F))[lane];

        float sc0 = wv.x * tanh_fast(pdv.x + p0.x)
                  + wv.y * tanh_fast(pdv.y + p0.y)
                  + wv.z * tanh_fast(pdv.z + p0.z)
                  + wv.w * tanh_fast(pdv.w + p0.w);
        float sc1 = wv.x * tanh_fast(pdv.x + p1.x)
                  + wv.y * tanh_fast(pdv.y + p1.y)
                  + wv.z * tanh_fast(pdv.z + p1.z)
                  + wv.w * tanh_fast(pdv.w + p1.w);
#pragma unroll
        for (int o = 16; o; o >>= 1) {
            sc0 += __shfl_xor_sync(0xffffffffu, sc0, o);
            sc1 += __shfl_xor_sync(0xffffffffu, sc1, o);
        }
        float ex0 = __expf(sc0);
        float ex1 = __expf(sc1);
        den += ex0 + ex1;
        acc.x = fmaf(ex0, f0.x, acc.x); acc.x = fmaf(ex1, f1.x, acc.x);
        acc.y = fmaf(ex0, f0.y, acc.y); acc.y = fmaf(ex1, f1.y, acc.y);
        acc.z = fmaf(ex0, f0.z, acc.z); acc.z = fmaf(ex1, f1.z, acc.z);
        acc.w = fmaf(ex0, f0.w, acc.w); acc.w = fmaf(ex1, f1.w, acc.w);
    }
    if (e < r1) {
        int s0 = __ldg(src + e);
        float4 p0 = ((const float4*)(g_ps + (size_t)s0 * F))[lane];
        float4 f0 = ((const float4*)(feat + (size_t)s0 * F))[lane];
        float sc0 = wv.x * tanh_fast(pdv.x + p0.x)
                  + wv.y * tanh_fast(pdv.y + p0.y)
                  + wv.z * tanh_fast(pdv.z + p0.z)
                  + wv.w * tanh_fast(pdv.w + p0.w);
#pragma unroll
        for (int o = 16; o; o >>= 1) sc0 += __shfl_xor_sync(0xffffffffu, sc0, o);
        float ex0 = __expf(sc0);
        den += ex0;
        acc.x = fmaf(ex0, f0.x, acc.x);
        acc.y = fmaf(ex0, f0.y, acc.y);
        acc.z = fmaf(ex0, f0.z, acc.z);
        acc.w = fmaf(ex0, f0.w, acc.w);
    }

    const float inv = (r1 > r0) ? (1.0f / den) : 0.f;
    uint4 o = {f2tf(acc.x * inv), f2tf(acc.y * inv),
               f2tf(acc.z * inv), f2tf(acc.w * inv)};
    ((uint4*)(g_nt + (size_t)node * F))[lane] = o;
}

// ---------------------------------------------------------------------------
extern "C" void kernel_launch(void* const* d_in, const int* in_sizes, int n_in,
                              void* d_out, int out_size)
{
    const float* feat = (const float*)d_in[0];
    const int*   src  = (const int*)d_in[1];
    const int*   dst  = (const int*)d_in[2];
    const float* w1   = (const float*)d_in[3];
    const float* b1   = (const float*)d_in[4];
    const float* w2   = (const float*)d_in[5];
    // d_in[6] = b2: cancels in softmax, unused
    const float* wf   = (const float*)d_in[7];
    const float* bf   = (const float*)d_in[8];
    float* out = (float*)d_out;

    const int N = in_sizes[0] / F;   // 40000
    const int E = in_sizes[1];       // 640000

    static int smem_set = 0;
    if (!smem_set) {
        cudaFuncSetAttribute(gemm_tf32,
            cudaFuncAttributeMaxDynamicSharedMemorySize, GEMM_SMEM);
        smem_set = 1;
    }

    float *pd, *ps;
    uint32_t *ft, *nt, *w1t, *wft;
    cudaGetSymbolAddress((void**)&pd,  g_pd);
    cudaGetSymbolAddress((void**)&ps,  g_ps);
    cudaGetSymbolAddress((void**)&ft,  g_ft);
    cudaGetSymbolAddress((void**)&nt,  g_nt);
    cudaGetSymbolAddress((void**)&w1t, g_w1t);
    cudaGetSymbolAddress((void**)&wft, g_wft);

    const int gblocks = (N + 127) / 128;   // 313

    // 0) pre-convert feat + weights to tf32
    conv_tf32<<<(N * F / 4 + 255) / 256, 256>>>(feat, ft, N * F / 4);
    conv_tf32<<<(2 * F * F / 4 + 255) / 256, 256>>>(w1, w1t, 2 * F * F / 4);
    conv_tf32<<<(2 * F * F / 4 + 255) / 256, 256>>>(wf, wft, 2 * F * F / 4);

    // 1) fused pair: pd = feat @ w1[:F] + b1 ; ps = feat @ w1[F:]
    gemm_tf32<<<dim3(gblocks, 2), 256, GEMM_SMEM>>>(
        ft, w1t, w1t + F * F, NULL, NULL, b1, NULL, pd, ps, N);

    // 2) CSR row pointers over sorted dst
    rowptr_kernel<<<(N + 1 + 255) / 256, 256>>>(dst, N, E);

    // 3) fused: scores + exp + denominator + weighted aggregation
    edge_fused_kernel<<<(N * 32 + 255) / 256, 256>>>(feat, src, w2, N);

    // 4) out = feat @ wf[:F] + neigh @ wf[F:] + bf  (dual-source GEMM)
    gemm_tf32<<<dim3(gblocks, 1), 256, GEMM_SMEM>>>(
        ft, wft, NULL, nt, wft + F * F, bf, NULL, out, NULL, N);
}